// round 2
// baseline (speedup 1.0000x reference)
#include <cuda_runtime.h>
#include <cuda_bf16.h>

// QuantumSelfAttention — closed-form collapse of the CRY-chain circuit.
//
// Reference circuit per row: product state amps (cos t_j, -i sin t_j) with
// t_j = (x_j + rot_j)/2, then CRY(e_j) chain (control j -> target j+1),
// then <Z_k>. Because the control-coherence terms trace out exactly, only the
// qubit-1 population propagates:
//   C_k   = cos(x_k + rot_k)              (= 1 - 2 sin^2 t_k, exact identity)
//   sp2_j = sin^2(e_j / 2)
//   out_0 = C_0
//   out_k = C_k * (1 - sp2_{k-1} * (1 - out_{k-1}))
// O(n) per row instead of O(n * 2^n) statevector simulation.

#define EMBED_DIM 10

__global__ __launch_bounds__(256)
void qsa_kernel(const float* __restrict__ x,      // [T, 10]
                const float* __restrict__ rot,    // [10]
                const float* __restrict__ ent,    // [9]
                float* __restrict__ out,          // [T, 10]
                int T)
{
    int t = blockIdx.x * blockDim.x + threadIdx.x;
    if (t >= T) return;

    // Row is 40 bytes => 8-byte aligned; load as 5x float2 (LDG.64).
    float xv[EMBED_DIM];
    const float2* px = reinterpret_cast<const float2*>(x + (size_t)t * EMBED_DIM);
#pragma unroll
    for (int i = 0; i < EMBED_DIM / 2; i++) {
        float2 v = __ldg(px + i);
        xv[2 * i]     = v.x;
        xv[2 * i + 1] = v.y;
    }

    float ov[EMBED_DIM];
    float prev = 0.0f;
#pragma unroll
    for (int k = 0; k < EMBED_DIM; k++) {
        float C = cosf(xv[k] + __ldg(rot + k));
        if (k == 0) {
            prev = C;
        } else {
            float sp  = sinf(0.5f * __ldg(ent + k - 1));
            float sp2 = sp * sp;
            // cp2 + sp2*prev = 1 - sp2*(1 - prev)
            prev = C * fmaf(sp2, prev - 1.0f, 1.0f);
        }
        ov[k] = prev;
    }

    float2* po = reinterpret_cast<float2*>(out + (size_t)t * EMBED_DIM);
#pragma unroll
    for (int i = 0; i < EMBED_DIM / 2; i++) {
        po[i] = make_float2(ov[2 * i], ov[2 * i + 1]);
    }
}

extern "C" void kernel_launch(void* const* d_in, const int* in_sizes, int n_in,
                              void* d_out, int out_size)
{
    const float* x   = (const float*)d_in[0];   // inputs [16,1024,10]
    const float* rot = (const float*)d_in[1];   // rotation_params [10]
    const float* ent = (const float*)d_in[2];   // entangle_params [9]
    float* out = (float*)d_out;

    int T = in_sizes[0] / EMBED_DIM;            // 16384 rows
    int threads = 256;
    int blocks = (T + threads - 1) / threads;
    qsa_kernel<<<blocks, threads>>>(x, rot, ent, out, T);
}

// round 3
// speedup vs baseline: 1.2019x; 1.2019x over previous
#include <cuda_runtime.h>
#include <cuda_bf16.h>

// QuantumSelfAttention — closed-form collapse of the CRY-chain circuit.
//
//   C_k   = cos(x_k + rot_k)
//   sp2_j = sin^2(e_j / 2)
//   out_0 = C_0
//   out_k = C_k * (1 - sp2_{k-1} * (1 - out_{k-1}))
//
// R2: latency-bound fix — 64-thread blocks (grid=256 covers all 148 SMs,
// vs 64 CTAs before) and MUFU-based __cosf/__sinf intrinsics (args are
// N(0,1)+rot, small; error << 1e-3 threshold) to shrink the per-thread
// dependent chain.

#define EMBED_DIM 10

__global__ __launch_bounds__(64)
void qsa_kernel(const float* __restrict__ x,      // [T, 10]
                const float* __restrict__ rot,    // [10]
                const float* __restrict__ ent,    // [9]
                float* __restrict__ out,          // [T, 10]
                int T)
{
    int t = blockIdx.x * blockDim.x + threadIdx.x;
    if (t >= T) return;

    // Row is 40 bytes => 8-byte aligned; 5x LDG.64, issued back-to-back (MLP=5).
    float xv[EMBED_DIM];
    const float2* px = reinterpret_cast<const float2*>(x + (size_t)t * EMBED_DIM);
#pragma unroll
    for (int i = 0; i < EMBED_DIM / 2; i++) {
        float2 v = __ldg(px + i);
        xv[2 * i]     = v.x;
        xv[2 * i + 1] = v.y;
    }

    // All 10 cosines are independent -> ILP while loads land.
    float C[EMBED_DIM];
#pragma unroll
    for (int k = 0; k < EMBED_DIM; k++) {
        C[k] = __cosf(xv[k] + __ldg(rot + k));
    }

    float ov[EMBED_DIM];
    float prev = C[0];
    ov[0] = prev;
#pragma unroll
    for (int k = 1; k < EMBED_DIM; k++) {
        float sp  = __sinf(0.5f * __ldg(ent + k - 1));
        float sp2 = sp * sp;
        // cp2 + sp2*prev = 1 - sp2*(1 - prev)
        prev = C[k] * fmaf(sp2, prev - 1.0f, 1.0f);
        ov[k] = prev;
    }

    float2* po = reinterpret_cast<float2*>(out + (size_t)t * EMBED_DIM);
#pragma unroll
    for (int i = 0; i < EMBED_DIM / 2; i++) {
        po[i] = make_float2(ov[2 * i], ov[2 * i + 1]);
    }
}

extern "C" void kernel_launch(void* const* d_in, const int* in_sizes, int n_in,
                              void* d_out, int out_size)
{
    const float* x   = (const float*)d_in[0];   // inputs [16,1024,10]
    const float* rot = (const float*)d_in[1];   // rotation_params [10]
    const float* ent = (const float*)d_in[2];   // entangle_params [9]
    float* out = (float*)d_out;

    int T = in_sizes[0] / EMBED_DIM;            // 16384 rows
    int threads = 64;
    int blocks = (T + threads - 1) / threads;   // 256 CTAs -> all 148 SMs
    qsa_kernel<<<blocks, threads>>>(x, rot, ent, out, T);
}

// round 4
// speedup vs baseline: 1.2195x; 1.0146x over previous
#include <cuda_runtime.h>
#include <cuda_bf16.h>

// QuantumSelfAttention — closed-form collapse of the CRY-chain circuit.
//
//   C_k   = cos(x_k + rot_k)
//   sp2_j = sin^2(e_j/2) = 0.5 - 0.5*cos(e_j)
//   out_0 = C_0
//   out_k = C_k * (1 - sp2_{k-1} * (1 - out_{k-1}))
//
// R3: small-kernel-floor regime. 2 rows per thread => 80B = 5x float4
// aligned loads/stores, shared sp2 across the row pair, and two
// interleaved recursion chains to hide dependent-FMA latency.
// 8192 threads as 256 CTAs x 32 threads (covers all 148 SMs).

#define EMBED_DIM 10

__global__ __launch_bounds__(32)
void qsa_kernel(const float4* __restrict__ x4,   // [T*10/4] float4 view of [T,10]
                const float* __restrict__ rot,   // [10]
                const float* __restrict__ ent,   // [9]
                float4* __restrict__ out4,       // float4 view of [T,10]
                int P)                           // P = T/2 row-pairs
{
    int p = blockIdx.x * blockDim.x + threadIdx.x;
    if (p >= P) return;

    // Row pair = 80 bytes = 5 x float4, 16B-aligned (80*p % 16 == 0).
    float xv[2 * EMBED_DIM];
    const float4* px = x4 + (size_t)p * 5;
#pragma unroll
    for (int i = 0; i < 5; i++) {
        float4 v = __ldg(px + i);
        xv[4 * i]     = v.x;
        xv[4 * i + 1] = v.y;
        xv[4 * i + 2] = v.z;
        xv[4 * i + 3] = v.w;
    }

    // sp2 shared by both rows: sin^2(e/2) = 0.5 - 0.5*cos(e)
    float sp2[EMBED_DIM - 1];
#pragma unroll
    for (int j = 0; j < EMBED_DIM - 1; j++) {
        sp2[j] = fmaf(-0.5f, __cosf(__ldg(ent + j)), 0.5f);
    }

    // 20 independent cosines — full ILP while loads land.
    float Ca[EMBED_DIM], Cb[EMBED_DIM];
#pragma unroll
    for (int k = 0; k < EMBED_DIM; k++) {
        float r = __ldg(rot + k);
        Ca[k] = __cosf(xv[k] + r);
        Cb[k] = __cosf(xv[EMBED_DIM + k] + r);
    }

    // Two interleaved serial recursions (rows a, b).
    float ov[2 * EMBED_DIM];
    float pa = Ca[0], pb = Cb[0];
    ov[0] = pa;
    ov[EMBED_DIM] = pb;
#pragma unroll
    for (int k = 1; k < EMBED_DIM; k++) {
        float s = sp2[k - 1];
        pa = Ca[k] * fmaf(s, pa - 1.0f, 1.0f);
        pb = Cb[k] * fmaf(s, pb - 1.0f, 1.0f);
        ov[k]             = pa;
        ov[EMBED_DIM + k] = pb;
    }

    float4* po = out4 + (size_t)p * 5;
#pragma unroll
    for (int i = 0; i < 5; i++) {
        po[i] = make_float4(ov[4 * i], ov[4 * i + 1], ov[4 * i + 2], ov[4 * i + 3]);
    }
}

extern "C" void kernel_launch(void* const* d_in, const int* in_sizes, int n_in,
                              void* d_out, int out_size)
{
    const float4* x4  = (const float4*)d_in[0];  // inputs [16,1024,10]
    const float* rot  = (const float*)d_in[1];   // rotation_params [10]
    const float* ent  = (const float*)d_in[2];   // entangle_params [9]
    float4* out4 = (float4*)d_out;

    int T = in_sizes[0] / EMBED_DIM;             // 16384 rows
    int P = T / 2;                               // 8192 row-pairs
    int threads = 32;
    int blocks = (P + threads - 1) / threads;    // 256 CTAs -> all 148 SMs
    qsa_kernel<<<blocks, threads>>>(x4, rot, ent, out4, P);
}